// round 3
// baseline (speedup 1.0000x reference)
#include <cuda_runtime.h>
#include <math.h>

#define L_  12
#define H_  12
#define D_  768
#define DH_ 64
#define FF_ 3072
#define B_  32
#define S_  256
#define NT_ (B_*S_)   /* 8192 tokens */

/* ---------------- scratch (device globals; no allocations) ---------------- */
__device__ float g_x[NT_*D_];
__device__ float g_q[NT_*D_];
__device__ float g_k[NT_*D_];
__device__ float g_v[NT_*D_];
__device__ float g_a[NT_*D_];
__device__ float g_t[NT_*D_];
__device__ float g_h[(size_t)NT_*FF_];
__device__ float g_sk[64*64];
__device__ float g_pq[32*64];

/* ---------------- block reduction (256 threads) ---------------- */
__device__ __forceinline__ float block_sum_256(float v, float* red) {
    int lane = threadIdx.x & 31, w = threadIdx.x >> 5;
    #pragma unroll
    for (int o = 16; o > 0; o >>= 1) v += __shfl_down_sync(0xffffffffu, v, o);
    if (lane == 0) red[w] = v;
    __syncthreads();
    if (w == 0) {
        float x = (lane < 8) ? red[lane] : 0.f;
        #pragma unroll
        for (int o = 4; o > 0; o >>= 1) x += __shfl_down_sync(0xffffffffu, x, o);
        if (lane == 0) red[32] = x;
    }
    __syncthreads();
    return red[32];
}

/* ---------------- embeddings + LayerNorm ---------------- */
__global__ void embed_ln_kernel(const int* __restrict__ ids, const int* __restrict__ tt,
                                const float* __restrict__ we, const float* __restrict__ pe,
                                const float* __restrict__ te, const float* __restrict__ g,
                                const float* __restrict__ b, float* __restrict__ x)
{
    int row = blockIdx.x;               /* b*S + s */
    int s = row & (S_-1);
    int id = ids[row], t = tt[row];
    __shared__ float buf[D_];
    __shared__ float red[40];
    int tid = threadIdx.x;
    float ps = 0.f;
    #pragma unroll
    for (int i = 0; i < 3; i++) {
        int d = tid + i*256;
        float e = we[(size_t)id*D_ + d] + pe[s*D_ + d] + te[t*D_ + d];
        buf[d] = e; ps += e;
    }
    __syncthreads();
    float mean = block_sum_256(ps, red) * (1.f/D_);
    float pv = 0.f;
    #pragma unroll
    for (int i = 0; i < 3; i++) { int d = tid + i*256; float c = buf[d]-mean; pv += c*c; }
    float var = block_sum_256(pv, red) * (1.f/D_);
    float inv = rsqrtf(var + 1e-12f);
    #pragma unroll
    for (int i = 0; i < 3; i++) {
        int d = tid + i*256;
        x[(size_t)row*D_ + d] = (buf[d]-mean)*inv*g[d] + b[d];
    }
}

/* ---------------- residual add + LayerNorm (in-place on x) ---------------- */
__global__ void add_ln_kernel(float* __restrict__ x, const float* __restrict__ t,
                              const float* __restrict__ g, const float* __restrict__ b)
{
    int row = blockIdx.x;
    __shared__ float buf[D_];
    __shared__ float red[40];
    int tid = threadIdx.x;
    float ps = 0.f;
    #pragma unroll
    for (int i = 0; i < 3; i++) {
        int d = tid + i*256;
        float e = x[(size_t)row*D_ + d] + t[(size_t)row*D_ + d];
        buf[d] = e; ps += e;
    }
    __syncthreads();
    float mean = block_sum_256(ps, red) * (1.f/D_);
    float pv = 0.f;
    #pragma unroll
    for (int i = 0; i < 3; i++) { int d = tid + i*256; float c = buf[d]-mean; pv += c*c; }
    float var = block_sum_256(pv, red) * (1.f/D_);
    float inv = rsqrtf(var + 1e-12f);
    #pragma unroll
    for (int i = 0; i < 3; i++) {
        int d = tid + i*256;
        x[(size_t)row*D_ + d] = (buf[d]-mean)*inv*g[d] + b[d];
    }
}

/* ---------------- classic 128x128x8 SGEMM, C = A@B + bias (opt GELU) ------
 * A [M,K] row-major, B [K,N] row-major, C [M,N] row-major.
 * M%128==0, N%128==0, K%8==0 guaranteed by problem shapes.            */
__global__ void sgemm_bias(const float* __restrict__ A, const float* __restrict__ B,
                           const float* __restrict__ bias, float* __restrict__ C,
                           int M, int N, int K, int gelu)
{
    const int BM = 128, BN = 128, BK = 8, TM = 8, TN = 8;
    __shared__ float As[BK][BM];
    __shared__ float Bs[BK][BN];
    int tid  = threadIdx.x;               /* 256 threads */
    int brow = blockIdx.y * BM;
    int bcol = blockIdx.x * BN;
    int trow = (tid >> 4) * TM;
    int tcol = (tid & 15) * TN;
    float acc[TM][TN];
    #pragma unroll
    for (int i = 0; i < TM; i++)
        #pragma unroll
        for (int j = 0; j < TN; j++) acc[i][j] = 0.f;

    int aRow = tid >> 1;                  /* 0..127 */
    int aCol = (tid & 1) * 4;             /* 0 or 4 */
    int bRow = tid >> 5;                  /* 0..7   */
    int bCol = (tid & 31) * 4;            /* 0..124 */
    const float* Aptr = A + (size_t)(brow + aRow) * K + aCol;
    const float* Bptr = B + (size_t)bRow * N + bcol + bCol;

    for (int k0 = 0; k0 < K; k0 += BK) {
        float4 a4 = *(const float4*)(Aptr + k0);
        As[aCol+0][aRow] = a4.x; As[aCol+1][aRow] = a4.y;
        As[aCol+2][aRow] = a4.z; As[aCol+3][aRow] = a4.w;
        float4 b4 = *(const float4*)(Bptr + (size_t)k0 * N);
        *(float4*)&Bs[bRow][bCol] = b4;
        __syncthreads();
        #pragma unroll
        for (int kk = 0; kk < BK; kk++) {
            float ra[TM], rb[TN];
            #pragma unroll
            for (int i = 0; i < TM; i++) ra[i] = As[kk][trow+i];
            #pragma unroll
            for (int j = 0; j < TN; j++) rb[j] = Bs[kk][tcol+j];
            #pragma unroll
            for (int i = 0; i < TM; i++)
                #pragma unroll
                for (int j = 0; j < TN; j++)
                    acc[i][j] += ra[i]*rb[j];
        }
        __syncthreads();
    }
    #pragma unroll
    for (int i = 0; i < TM; i++) {
        int row = brow + trow + i;
        #pragma unroll
        for (int j = 0; j < TN; j++) {
            int col = bcol + tcol + j;
            float c = acc[i][j] + bias[col];
            if (gelu) c = 0.5f*c*(1.f + erff(c*0.70710678118654752f));
            C[(size_t)row*N + col] = c;
        }
    }
}

/* ---------------- fused attention: online softmax, per (b,h,half) -------- */
__global__ void attention_kernel(const float* __restrict__ q, const float* __restrict__ k,
                                 const float* __restrict__ v, const int* __restrict__ mask,
                                 float* __restrict__ o)
{
    int half = blockIdx.x;   /* 0..1  */
    int h    = blockIdx.y;   /* 0..11 */
    int b    = blockIdx.z;   /* 0..31 */
    int qi   = half*128 + threadIdx.x;   /* query index, one per thread */
    __shared__ float Ks[64][68];
    __shared__ float Vs[64][68];
    __shared__ float mb[64];

    const size_t base = (size_t)b * S_ * D_ + (size_t)h * DH_;
    float qreg[64];
    #pragma unroll
    for (int d = 0; d < 64; d++) qreg[d] = q[base + (size_t)qi*D_ + d];
    float acc[64];
    #pragma unroll
    for (int d = 0; d < 64; d++) acc[d] = 0.f;
    float m = -1e30f, l = 0.f;

    int r  = threadIdx.x >> 1;            /* 0..63 */
    int cc = (threadIdx.x & 1) * 32;      /* 0 or 32 */

    for (int c0 = 0; c0 < S_; c0 += 64) {
        #pragma unroll
        for (int j = 0; j < 32; j += 4) {
            float4 k4 = *(const float4*)(k + base + (size_t)(c0+r)*D_ + cc + j);
            float4 v4 = *(const float4*)(v + base + (size_t)(c0+r)*D_ + cc + j);
            *(float4*)&Ks[r][cc+j] = k4;
            *(float4*)&Vs[r][cc+j] = v4;
        }
        if (threadIdx.x < 64)
            mb[threadIdx.x] = mask[b*S_ + c0 + threadIdx.x] ? 0.f : -10000.f;
        __syncthreads();

        for (int kk = 0; kk < 64; kk++) {
            float s = 0.f;
            #pragma unroll
            for (int d = 0; d < 64; d++) s += qreg[d]*Ks[kk][d];
            s = s*0.125f + mb[kk];
            float nm = fmaxf(m, s);
            float sc = expf(m - nm);
            float p  = expf(s - nm);
            l = l*sc + p;
            #pragma unroll
            for (int d = 0; d < 64; d++) acc[d] = acc[d]*sc + p*Vs[kk][d];
            m = nm;
        }
        __syncthreads();
    }
    float inv = 1.f / l;
    #pragma unroll
    for (int d = 0; d < 64; d++)
        o[base + (size_t)qi*D_ + d] = acc[d]*inv;
}

/* ---------------- sense head ---------------- */
__global__ void sense_proj_kernel(const float* __restrict__ sense_emb,
                                  const float* __restrict__ att_Wk, float* __restrict__ sk)
{
    int idx = blockIdx.x*256 + threadIdx.x;   /* 4096 = 64*64 */
    int j = idx >> 6, a = idx & 63;
    float s = 0.f;
    for (int d = 0; d < D_; d++)
        s += sense_emb[(size_t)j*D_ + d] * att_Wk[(size_t)d*64 + a];
    sk[idx] = s;
}

__global__ void pun_proj_kernel(const float* __restrict__ x, const int* __restrict__ loc,
                                const float* __restrict__ att_Wq, float* __restrict__ pq)
{
    int idx = blockIdx.x*256 + threadIdx.x;   /* 2048 = 32*64 */
    int b = idx >> 6, a = idx & 63;
    int row = b*S_ + loc[b];
    float s = 0.f;
    for (int d = 0; d < D_; d++)
        s += x[(size_t)row*D_ + d] * att_Wq[(size_t)d*64 + a];
    pq[idx] = s;
}

__global__ void top2_kernel(const float* __restrict__ pq, const float* __restrict__ sk,
                            float* __restrict__ out)
{
    int b = blockIdx.x, j = threadIdx.x;      /* 64 threads */
    __shared__ float sc[64];
    float s = 0.f;
    #pragma unroll 8
    for (int a = 0; a < 64; a++) s += pq[b*64 + a] * sk[j*64 + a];
    sc[j] = s * 0.125f;                       /* /sqrt(64); softmax monotone -> skip */
    __syncthreads();
    if (j == 0) {
        int i1 = 0; float v1 = sc[0];
        for (int i = 1; i < 64; i++) if (sc[i] > v1) { v1 = sc[i]; i1 = i; }
        int i2 = -1; float v2 = -1e30f;
        for (int i = 0; i < 64; i++) if (i != i1 && sc[i] > v2) { v2 = sc[i]; i2 = i; }
        out[b*2 + 0] = (float)i1;
        out[b*2 + 1] = (float)i2;
    }
}

/* ---------------- launch ---------------- */
extern "C" void kernel_launch(void* const* d_in, const int* in_sizes, int n_in,
                              void* d_out, int out_size)
{
    (void)in_sizes; (void)n_in; (void)out_size;
    const int*   input_ids = (const int*)  d_in[0];
    const int*   token_tt  = (const int*)  d_in[1];
    const int*   attn_mask = (const int*)  d_in[2];
    const int*   location  = (const int*)  d_in[3];
    const float* sense_emb = (const float*)d_in[4];
    const float* word_emb  = (const float*)d_in[5];
    const float* pos_emb   = (const float*)d_in[6];
    const float* type_emb  = (const float*)d_in[7];
    const float* emb_ln_g  = (const float*)d_in[8];
    const float* emb_ln_b  = (const float*)d_in[9];
    const float* Wq  = (const float*)d_in[10]; const float* bq  = (const float*)d_in[11];
    const float* Wk  = (const float*)d_in[12]; const float* bk  = (const float*)d_in[13];
    const float* Wv  = (const float*)d_in[14]; const float* bv  = (const float*)d_in[15];
    const float* Wo  = (const float*)d_in[16]; const float* bo  = (const float*)d_in[17];
    const float* ln1g= (const float*)d_in[18]; const float* ln1b= (const float*)d_in[19];
    const float* W1  = (const float*)d_in[20]; const float* b1  = (const float*)d_in[21];
    const float* W2  = (const float*)d_in[22]; const float* b2  = (const float*)d_in[23];
    const float* ln2g= (const float*)d_in[24]; const float* ln2b= (const float*)d_in[25];
    const float* attWq=(const float*)d_in[26]; const float* attWk=(const float*)d_in[27];
    float* out = (float*)d_out;

    float *x,*q,*k,*v,*a,*t,*h,*sk,*pq;
    cudaGetSymbolAddress((void**)&x,  g_x);
    cudaGetSymbolAddress((void**)&q,  g_q);
    cudaGetSymbolAddress((void**)&k,  g_k);
    cudaGetSymbolAddress((void**)&v,  g_v);
    cudaGetSymbolAddress((void**)&a,  g_a);
    cudaGetSymbolAddress((void**)&t,  g_t);
    cudaGetSymbolAddress((void**)&h,  g_h);
    cudaGetSymbolAddress((void**)&sk, g_sk);
    cudaGetSymbolAddress((void**)&pq, g_pq);

    embed_ln_kernel<<<NT_, 256>>>(input_ids, token_tt, word_emb, pos_emb, type_emb,
                                  emb_ln_g, emb_ln_b, x);

    dim3 gD(D_/128,  NT_/128);   /* N=768  */
    dim3 gF(FF_/128, NT_/128);   /* N=3072 */

    for (int l = 0; l < L_; l++) {
        size_t wDD = (size_t)l*D_*D_;
        size_t wDF = (size_t)l*D_*FF_;
        sgemm_bias<<<gD, 256>>>(x, Wq + wDD, bq + l*D_, q, NT_, D_, D_, 0);
        sgemm_bias<<<gD, 256>>>(x, Wk + wDD, bk + l*D_, k, NT_, D_, D_, 0);
        sgemm_bias<<<gD, 256>>>(x, Wv + wDD, bv + l*D_, v, NT_, D_, D_, 0);
        attention_kernel<<<dim3(2, H_, B_), 128>>>(q, k, v, attn_mask, a);
        sgemm_bias<<<gD, 256>>>(a, Wo + wDD, bo + l*D_, t, NT_, D_, D_, 0);
        add_ln_kernel<<<NT_, 256>>>(x, t, ln1g + l*D_, ln1b + l*D_);
        sgemm_bias<<<gF, 256>>>(x, W1 + wDF, b1 + l*FF_, h, NT_, FF_, D_, 1);
        sgemm_bias<<<gD, 256>>>(h, W2 + wDF, b2 + l*D_, t, NT_, D_, FF_, 0);
        add_ln_kernel<<<NT_, 256>>>(x, t, ln2g + l*D_, ln2b + l*D_);
    }

    sense_proj_kernel<<<16, 256>>>(sense_emb, attWk, sk);
    pun_proj_kernel<<<8, 256>>>(x, location, attWq, pq);
    top2_kernel<<<B_, 64>>>(pq, sk, out);
}

// round 4
// speedup vs baseline: 2.7839x; 2.7839x over previous
#include <cuda_runtime.h>
#include <math.h>
#include <stdint.h>

#define L_  12
#define H_  12
#define D_  768
#define DH_ 64
#define FF_ 3072
#define B_  32
#define S_  256
#define NT_ (B_*S_)   /* 8192 tokens */

/* ---------------- scratch (device globals; no allocations) ---------------- */
__device__ float g_x[NT_*D_];
__device__ float g_q[NT_*D_];
__device__ float g_k[NT_*D_];
__device__ float g_v[NT_*D_];
__device__ float g_a[NT_*D_];
__device__ float g_t[NT_*D_];
__device__ float g_h[(size_t)NT_*FF_];
__device__ float g_sk[64*64];
__device__ float g_pq[32*64];

/* ---------------- block reduction (256 threads) ---------------- */
__device__ __forceinline__ float block_sum_256(float v, float* red) {
    int lane = threadIdx.x & 31, w = threadIdx.x >> 5;
    #pragma unroll
    for (int o = 16; o > 0; o >>= 1) v += __shfl_down_sync(0xffffffffu, v, o);
    if (lane == 0) red[w] = v;
    __syncthreads();
    if (w == 0) {
        float x = (lane < 8) ? red[lane] : 0.f;
        #pragma unroll
        for (int o = 4; o > 0; o >>= 1) x += __shfl_down_sync(0xffffffffu, x, o);
        if (lane == 0) red[32] = x;
    }
    __syncthreads();
    return red[32];
}

/* ---------------- embeddings + LayerNorm ---------------- */
__global__ void embed_ln_kernel(const int* __restrict__ ids, const int* __restrict__ tt,
                                const float* __restrict__ we, const float* __restrict__ pe,
                                const float* __restrict__ te, const float* __restrict__ g,
                                const float* __restrict__ b, float* __restrict__ x)
{
    int row = blockIdx.x;
    int s = row & (S_-1);
    int id = ids[row], t = tt[row];
    __shared__ float buf[D_];
    __shared__ float red[40];
    int tid = threadIdx.x;
    float ps = 0.f;
    #pragma unroll
    for (int i = 0; i < 3; i++) {
        int d = tid + i*256;
        float e = we[(size_t)id*D_ + d] + pe[s*D_ + d] + te[t*D_ + d];
        buf[d] = e; ps += e;
    }
    __syncthreads();
    float mean = block_sum_256(ps, red) * (1.f/D_);
    float pv = 0.f;
    #pragma unroll
    for (int i = 0; i < 3; i++) { int d = tid + i*256; float c = buf[d]-mean; pv += c*c; }
    float var = block_sum_256(pv, red) * (1.f/D_);
    float inv = rsqrtf(var + 1e-12f);
    #pragma unroll
    for (int i = 0; i < 3; i++) {
        int d = tid + i*256;
        x[(size_t)row*D_ + d] = (buf[d]-mean)*inv*g[d] + b[d];
    }
}

/* ---------------- residual add + LayerNorm (in-place on x) ---------------- */
__global__ void add_ln_kernel(float* __restrict__ x, const float* __restrict__ t,
                              const float* __restrict__ g, const float* __restrict__ b)
{
    int row = blockIdx.x;
    __shared__ float buf[D_];
    __shared__ float red[40];
    int tid = threadIdx.x;
    float ps = 0.f;
    #pragma unroll
    for (int i = 0; i < 3; i++) {
        int d = tid + i*256;
        float e = x[(size_t)row*D_ + d] + t[(size_t)row*D_ + d];
        buf[d] = e; ps += e;
    }
    __syncthreads();
    float mean = block_sum_256(ps, red) * (1.f/D_);
    float pv = 0.f;
    #pragma unroll
    for (int i = 0; i < 3; i++) { int d = tid + i*256; float c = buf[d]-mean; pv += c*c; }
    float var = block_sum_256(pv, red) * (1.f/D_);
    float inv = rsqrtf(var + 1e-12f);
    #pragma unroll
    for (int i = 0; i < 3; i++) {
        int d = tid + i*256;
        x[(size_t)row*D_ + d] = (buf[d]-mean)*inv*g[d] + b[d];
    }
}

/* ================= tf32 tensor-core GEMM =================
 * C[M,N] = A[M,K] @ B[K,N] + bias (opt exact GELU)
 * block 128x128, BK=16, 8 warps (2x4), warp tile 64x32,
 * mma.sync.aligned.m16n8k8 tf32, cp.async double-buffered.
 * Requires M%128==0, N%128==0, K%16==0 (true for all shapes here). */

__device__ __forceinline__ void cpasync16(void* smem, const void* gmem) {
    uint32_t s = (uint32_t)__cvta_generic_to_shared(smem);
    asm volatile("cp.async.ca.shared.global [%0], [%1], 16;\n" :: "r"(s), "l"(gmem));
}
__device__ __forceinline__ void cp_commit() { asm volatile("cp.async.commit_group;\n"); }
__device__ __forceinline__ void cp_wait0()  { asm volatile("cp.async.wait_group 0;\n"); }

__device__ __forceinline__ void mma_tf32(float* d, const uint32_t* a, const uint32_t* b) {
    asm volatile(
        "mma.sync.aligned.m16n8k8.row.col.f32.tf32.tf32.f32 "
        "{%0,%1,%2,%3}, {%4,%5,%6,%7}, {%8,%9}, {%0,%1,%2,%3};\n"
        : "+f"(d[0]), "+f"(d[1]), "+f"(d[2]), "+f"(d[3])
        : "r"(a[0]), "r"(a[1]), "r"(a[2]), "r"(a[3]), "r"(b[0]), "r"(b[1]));
}

#define APAD 20   /* As row stride (floats): 16 + 4, conflict-free fragment reads */
#define BPAD 136  /* Bs row stride (floats): 128 + 8, conflict-free fragment reads */

__global__ __launch_bounds__(256, 2)
void sgemm_tf32(const float* __restrict__ A, const float* __restrict__ B,
                const float* __restrict__ bias, float* __restrict__ C,
                int M, int N, int K, int gelu)
{
    __shared__ __align__(16) float As[2][128][APAD];
    __shared__ __align__(16) float Bs[2][16][BPAD];

    const int tid  = threadIdx.x;
    const int brow = blockIdx.y * 128;
    const int bcol = blockIdx.x * 128;
    const int lane = tid & 31;
    const int wid  = tid >> 5;
    const int g    = lane >> 2;      /* groupID 0..7 */
    const int tg   = lane & 3;       /* thread-in-group 0..3 */
    const int wm   = (wid & 1) * 64; /* warp row base in block */
    const int wn   = (wid >> 1) * 32;/* warp col base in block */

    float acc[4][4][4];
    #pragma unroll
    for (int mt = 0; mt < 4; mt++)
        #pragma unroll
        for (int nt = 0; nt < 4; nt++)
            #pragma unroll
            for (int i = 0; i < 4; i++) acc[mt][nt][i] = 0.f;

    /* stage loader: A tile 128x16 (512 16B chunks), B tile 16x128 (512 chunks) */
    const int am = tid >> 2, akc = (tid & 3) << 2;           /* A: 256 threads -> 2 chunks each */
    const int am2 = (tid + 256) >> 2, akc2 = ((tid + 256) & 3) << 2;
    const int bk = tid >> 5, bnc = (tid & 31) << 2;
    const int bk2 = (tid + 256) >> 5, bnc2 = ((tid + 256) & 31) << 2;

    #define LOAD_STAGE(buf, k0) do {                                                    \
        cpasync16(&As[buf][am ][akc ], A + (size_t)(brow + am )*K + (k0) + akc );        \
        cpasync16(&As[buf][am2][akc2], A + (size_t)(brow + am2)*K + (k0) + akc2);        \
        cpasync16(&Bs[buf][bk ][bnc ], B + (size_t)((k0) + bk )*N + bcol + bnc );        \
        cpasync16(&Bs[buf][bk2][bnc2], B + (size_t)((k0) + bk2)*N + bcol + bnc2);        \
    } while (0)

    LOAD_STAGE(0, 0);
    cp_commit();

    const int nk = K >> 4;
    for (int it = 0; it < nk; it++) {
        cp_wait0();
        __syncthreads();
        const int cur = it & 1;
        if (it + 1 < nk) LOAD_STAGE(cur ^ 1, (it + 1) << 4);
        cp_commit();

        #pragma unroll
        for (int kk = 0; kk < 16; kk += 8) {
            uint32_t afr[4][4];
            #pragma unroll
            for (int mt = 0; mt < 4; mt++) {
                int m = wm + mt*16;
                afr[mt][0] = __float_as_uint(As[cur][m + g    ][kk + tg    ]);
                afr[mt][1] = __float_as_uint(As[cur][m + g + 8][kk + tg    ]);
                afr[mt][2] = __float_as_uint(As[cur][m + g    ][kk + tg + 4]);
                afr[mt][3] = __float_as_uint(As[cur][m + g + 8][kk + tg + 4]);
            }
            uint32_t bfr[4][2];
            #pragma unroll
            for (int nt = 0; nt < 4; nt++) {
                int n = wn + nt*8;
                bfr[nt][0] = __float_as_uint(Bs[cur][kk + tg    ][n + g]);
                bfr[nt][1] = __float_as_uint(Bs[cur][kk + tg + 4][n + g]);
            }
            #pragma unroll
            for (int mt = 0; mt < 4; mt++)
                #pragma unroll
                for (int nt = 0; nt < 4; nt++)
                    mma_tf32(acc[mt][nt], afr[mt], bfr[nt]);
        }
    }

    /* epilogue: bias (+ optional exact GELU), float2 stores */
    #pragma unroll
    for (int mt = 0; mt < 4; mt++) {
        #pragma unroll
        for (int nt = 0; nt < 4; nt++) {
            int row0 = brow + wm + mt*16 + g;
            int col  = bcol + wn + nt*8 + tg*2;
            float b0 = bias[col], b1 = bias[col + 1];
            float c0 = acc[mt][nt][0] + b0;
            float c1 = acc[mt][nt][1] + b1;
            float c2 = acc[mt][nt][2] + b0;
            float c3 = acc[mt][nt][3] + b1;
            if (gelu) {
                c0 = 0.5f*c0*(1.f + erff(c0*0.70710678118654752f));
                c1 = 0.5f*c1*(1.f + erff(c1*0.70710678118654752f));
                c2 = 0.5f*c2*(1.f + erff(c2*0.70710678118654752f));
                c3 = 0.5f*c3*(1.f + erff(c3*0.70710678118654752f));
            }
            *(float2*)(C + (size_t)row0*N + col)       = make_float2(c0, c1);
            *(float2*)(C + (size_t)(row0 + 8)*N + col) = make_float2(c2, c3);
        }
    }
}

/* ---------------- fused attention: online softmax, per (b,h,half) -------- */
__global__ void attention_kernel(const float* __restrict__ q, const float* __restrict__ k,
                                 const float* __restrict__ v, const int* __restrict__ mask,
                                 float* __restrict__ o)
{
    int half = blockIdx.x;
    int h    = blockIdx.y;
    int b    = blockIdx.z;
    int qi   = half*128 + threadIdx.x;
    __shared__ float Ks[64][68];
    __shared__ float Vs[64][68];
    __shared__ float mb[64];

    const size_t base = (size_t)b * S_ * D_ + (size_t)h * DH_;
    float qreg[64];
    #pragma unroll
    for (int d = 0; d < 64; d++) qreg[d] = q[base + (size_t)qi*D_ + d];
    float acc[64];
    #pragma unroll
    for (int d = 0; d < 64; d++) acc[d] = 0.f;
    float m = -1e30f, l = 0.f;

    int r  = threadIdx.x >> 1;
    int cc = (threadIdx.x & 1) * 32;

    for (int c0 = 0; c0 < S_; c0 += 64) {
        #pragma unroll
        for (int j = 0; j < 32; j += 4) {
            float4 k4 = *(const float4*)(k + base + (size_t)(c0+r)*D_ + cc + j);
            float4 v4 = *(const float4*)(v + base + (size_t)(c0+r)*D_ + cc + j);
            *(float4*)&Ks[r][cc+j] = k4;
            *(float4*)&Vs[r][cc+j] = v4;
        }
        if (threadIdx.x < 64)
            mb[threadIdx.x] = mask[b*S_ + c0 + threadIdx.x] ? 0.f : -10000.f;
        __syncthreads();

        for (int kk = 0; kk < 64; kk++) {
            float s = 0.f;
            #pragma unroll
            for (int d = 0; d < 64; d++) s += qreg[d]*Ks[kk][d];
            s = s*0.125f + mb[kk];
            float nm = fmaxf(m, s);
            float sc = expf(m - nm);
            float p  = expf(s - nm);
            l = l*sc + p;
            #pragma unroll
            for (int d = 0; d < 64; d++) acc[d] = acc[d]*sc + p*Vs[kk][d];
            m = nm;
        }
        __syncthreads();
    }
    float inv = 1.f / l;
    #pragma unroll
    for (int d = 0; d < 64; d++)
        o[base + (size_t)qi*D_ + d] = acc[d]*inv;
}

/* ---------------- sense head ---------------- */
__global__ void sense_proj_kernel(const float* __restrict__ sense_emb,
                                  const float* __restrict__ att_Wk, float* __restrict__ sk)
{
    int idx = blockIdx.x*256 + threadIdx.x;
    int j = idx >> 6, a = idx & 63;
    float s = 0.f;
    for (int d = 0; d < D_; d++)
        s += sense_emb[(size_t)j*D_ + d] * att_Wk[(size_t)d*64 + a];
    sk[idx] = s;
}

__global__ void pun_proj_kernel(const float* __restrict__ x, const int* __restrict__ loc,
                                const float* __restrict__ att_Wq, float* __restrict__ pq)
{
    int idx = blockIdx.x*256 + threadIdx.x;
    int b = idx >> 6, a = idx & 63;
    int row = b*S_ + loc[b];
    float s = 0.f;
    for (int d = 0; d < D_; d++)
        s += x[(size_t)row*D_ + d] * att_Wq[(size_t)d*64 + a];
    pq[idx] = s;
}

__global__ void top2_kernel(const float* __restrict__ pq, const float* __restrict__ sk,
                            float* __restrict__ out)
{
    int b = blockIdx.x, j = threadIdx.x;
    __shared__ float sc[64];
    float s = 0.f;
    #pragma unroll 8
    for (int a = 0; a < 64; a++) s += pq[b*64 + a] * sk[j*64 + a];
    sc[j] = s * 0.125f;
    __syncthreads();
    if (j == 0) {
        int i1 = 0; float v1 = sc[0];
        for (int i = 1; i < 64; i++) if (sc[i] > v1) { v1 = sc[i]; i1 = i; }
        int i2 = -1; float v2 = -1e30f;
        for (int i = 0; i < 64; i++) if (i != i1 && sc[i] > v2) { v2 = sc[i]; i2 = i; }
        out[b*2 + 0] = (float)i1;
        out[b*2 + 1] = (float)i2;
    }
}

/* ---------------- launch ---------------- */
extern "C" void kernel_launch(void* const* d_in, const int* in_sizes, int n_in,
                              void* d_out, int out_size)
{
    (void)in_sizes; (void)n_in; (void)out_size;
    const int*   input_ids = (const int*)  d_in[0];
    const int*   token_tt  = (const int*)  d_in[1];
    const int*   attn_mask = (const int*)  d_in[2];
    const int*   location  = (const int*)  d_in[3];
    const float* sense_emb = (const float*)d_in[4];
    const float* word_emb  = (const float*)d_in[5];
    const float* pos_emb   = (const float*)d_in[6];
    const float* type_emb  = (const float*)d_in[7];
    const float* emb_ln_g  = (const float*)d_in[8];
    const float* emb_ln_b  = (const float*)d_in[9];
    const float* Wq  = (const float*)d_in[10]; const float* bq  = (const float*)d_in[11];
    const float* Wk  = (const float*)d_in[12]; const float* bk  = (const float*)d_in[13];
    const float* Wv  = (const float*)d_in[14]; const float* bv  = (const float*)d_in[15];
    const float* Wo  = (const float*)d_in[16]; const float* bo  = (const float*)d_in[17];
    const float* ln1g= (const float*)d_in[18]; const float* ln1b= (const float*)d_in[19];
    const float* W1  = (const float*)d_in[20]; const float* b1  = (const float*)d_in[21];
    const float* W2  = (const float*)d_in[22]; const float* b2  = (const float*)d_in[23];
    const float* ln2g= (const float*)d_in[24]; const float* ln2b= (const float*)d_in[25];
    const float* attWq=(const float*)d_in[26]; const float* attWk=(const float*)d_in[27];
    float* out = (float*)d_out;

    float *x,*q,*k,*v,*a,*t,*h,*sk,*pq;
    cudaGetSymbolAddress((void**)&x,  g_x);
    cudaGetSymbolAddress((void**)&q,  g_q);
    cudaGetSymbolAddress((void**)&k,  g_k);
    cudaGetSymbolAddress((void**)&v,  g_v);
    cudaGetSymbolAddress((void**)&a,  g_a);
    cudaGetSymbolAddress((void**)&t,  g_t);
    cudaGetSymbolAddress((void**)&h,  g_h);
    cudaGetSymbolAddress((void**)&sk, g_sk);
    cudaGetSymbolAddress((void**)&pq, g_pq);

    embed_ln_kernel<<<NT_, 256>>>(input_ids, token_tt, word_emb, pos_emb, type_emb,
                                  emb_ln_g, emb_ln_b, x);

    dim3 gD(D_/128,  NT_/128);   /* N=768  */
    dim3 gF(FF_/128, NT_/128);   /* N=3072 */

    for (int l = 0; l < L_; l++) {
        size_t wDD = (size_t)l*D_*D_;
        size_t wDF = (size_t)l*D_*FF_;
        sgemm_tf32<<<gD, 256>>>(x, Wq + wDD, bq + l*D_, q, NT_, D_, D_, 0);
        sgemm_tf32<<<gD, 256>>>(x, Wk + wDD, bk + l*D_, k, NT_, D_, D_, 0);
        sgemm_tf32<<<gD, 256>>>(x, Wv + wDD, bv + l*D_, v, NT_, D_, D_, 0);
        attention_kernel<<<dim3(2, H_, B_), 128>>>(q, k, v, attn_mask, a);
        sgemm_tf32<<<gD, 256>>>(a, Wo + wDD, bo + l*D_, t, NT_, D_, D_, 0);
        add_ln_kernel<<<NT_, 256>>>(x, t, ln1g + l*D_, ln1b + l*D_);
        sgemm_tf32<<<gF, 256>>>(x, W1 + wDF, b1 + l*FF_, h, NT_, FF_, D_, 1);
        sgemm_tf32<<<gD, 256>>>(h, W2 + wDF, b2 + l*D_, t, NT_, D_, FF_, 0);
        add_ln_kernel<<<NT_, 256>>>(x, t, ln2g + l*D_, ln2b + l*D_);
    }

    sense_proj_kernel<<<16, 256>>>(sense_emb, attWk, sk);
    pun_proj_kernel<<<8, 256>>>(x, location, attWq, pq);
    top2_kernel<<<B_, 64>>>(pq, sk, out);
}